// round 2
// baseline (speedup 1.0000x reference)
#include <cuda_runtime.h>
#include <math.h>
#include <stdint.h>

// Problem constants
#define B_ 2
#define N_ 8192
#define C_ 256
#define H_ 8
#define CH_ 32
#define M_ 32
#define HID_ 512
#define TAB_ 3025
#define NTOK (B_*N_)   // 16384

// ---------------- scratch (device globals; no allocation allowed) ------------
__device__ float g_w1[768*256];   // packed [q_w*scale ; kv_w]
__device__ float g_b1[768];       // packed [q_b*scale ; kv_b]
__device__ float g_pe[TAB_*H_];   // pe_table [TAB, H]
__device__ float g_xln[NTOK*C_];  // LN1(feat) and reused for LN2 output? (kept separate below)
__device__ float g_q[NTOK*C_];
__device__ float g_k[NTOK*C_];
__device__ float g_v[NTOK*C_];
__device__ float g_ao[NTOK*C_];   // attention output (pre-proj)
__device__ float g_x[NTOK*C_];    // post-attention residual
__device__ float g_xln2[NTOK*C_];
__device__ float g_h1[NTOK*HID_]; // fc1+gelu output

// ---------------- prep: pack W1/b1, compute pe_table -------------------------
__global__ void prep_kernel(const float* __restrict__ qw, const float* __restrict__ qb,
                            const float* __restrict__ kvw, const float* __restrict__ kvb,
                            const float* __restrict__ pre, const float* __restrict__ pew,
                            const float* __restrict__ peb)
{
    const float scale = 0.17677669529663687f; // 32^-0.5
    int t = blockIdx.x * blockDim.x + threadIdx.x;
    if (t < 256*256)        g_w1[t] = qw[t] * scale;
    else if (t < 768*256)   g_w1[t] = kvw[t - 256*256];
    if (t < 256)            g_b1[t] = qb[t] * scale;
    else if (t < 768)       g_b1[t] = kvb[t - 256];
    if (t < TAB_*H_) {
        int tab = t >> 3, h = t & 7;
        float s = peb[h];
        #pragma unroll
        for (int f = 0; f < 5; f++) s += pre[tab*5 + f] * pew[h*5 + f];
        g_pe[t] = s;
    }
}

// ---------------- LayerNorm: one warp per token -------------------------------
// WHICH=0: in = feat (param), out = g_xln.  WHICH=1: in = g_x, out = g_xln2.
template<int WHICH>
__global__ void ln_kernel(const float* __restrict__ xin,
                          const float* __restrict__ w, const float* __restrict__ b)
{
    int gw   = (blockIdx.x * blockDim.x + threadIdx.x) >> 5;
    int lane = threadIdx.x & 31;
    if (gw >= NTOK) return;
    const float* src = (WHICH == 0) ? xin : g_x;
    float*       dst = (WHICH == 0) ? g_xln : g_xln2;
    const float4* xr = (const float4*)(src + (size_t)gw * C_);
    float4 a = xr[lane*2], c = xr[lane*2 + 1];
    float s  = a.x + a.y + a.z + a.w + c.x + c.y + c.z + c.w;
    float ss = a.x*a.x + a.y*a.y + a.z*a.z + a.w*a.w
             + c.x*c.x + c.y*c.y + c.z*c.z + c.w*c.w;
    #pragma unroll
    for (int o = 16; o > 0; o >>= 1) {
        s  += __shfl_xor_sync(0xffffffffu, s,  o);
        ss += __shfl_xor_sync(0xffffffffu, ss, o);
    }
    float mean = s * (1.0f/256.0f);
    float var  = ss * (1.0f/256.0f) - mean*mean;
    float rstd = rsqrtf(var + 1e-5f);
    int c0 = lane * 8;
    float4 w0 = *(const float4*)(w + c0), w1 = *(const float4*)(w + c0 + 4);
    float4 b0 = *(const float4*)(b + c0), b1 = *(const float4*)(b + c0 + 4);
    float4 o0, o1;
    o0.x = (a.x-mean)*rstd*w0.x + b0.x;  o0.y = (a.y-mean)*rstd*w0.y + b0.y;
    o0.z = (a.z-mean)*rstd*w0.z + b0.z;  o0.w = (a.w-mean)*rstd*w0.w + b0.w;
    o1.x = (c.x-mean)*rstd*w1.x + b1.x;  o1.y = (c.y-mean)*rstd*w1.y + b1.y;
    o1.z = (c.z-mean)*rstd*w1.z + b1.z;  o1.w = (c.w-mean)*rstd*w1.w + b1.w;
    float4* yr = (float4*)(dst + (size_t)gw * C_);
    yr[lane*2] = o0; yr[lane*2 + 1] = o1;
}

// ---------------- SGEMM (NT): C[M,N] = A[M,K] @ W[N,K]^T + epilogue ----------
// MODE 0: QKV   A=g_xln,  W=g_w1,   bias=g_b1, scatter -> g_q/g_k/g_v
// MODE 1: proj  A=g_ao,   W=param,  bias=param, +res(feat param) -> g_x
// MODE 2: fc1   A=g_xln2, W=param,  bias=param, gelu -> g_h1
// MODE 3: fc2   A=g_h1,   W=param,  bias=param, +res(g_x) -> out param
#define BM 128
#define BN 128
#define BKK 16

__device__ __forceinline__ float gelu_exact(float v)
{
    return 0.5f * v * (1.0f + erff(v * 0.70710678118654752f));
}

template<int MODE>
__global__ void __launch_bounds__(256) sgemm_nt(const float* __restrict__ Wp,
                                                const float* __restrict__ biasp,
                                                const float* __restrict__ resp,
                                                float* __restrict__ outp,
                                                int Nw, int K)
{
    const float* A  = (MODE == 0) ? g_xln : (MODE == 1) ? g_ao : (MODE == 2) ? g_xln2 : g_h1;
    const float* Wm = (MODE == 0) ? g_w1 : Wp;
    const float* bi = (MODE == 0) ? g_b1 : biasp;

    __shared__ float As[BKK][BM + 4];
    __shared__ float Bs[BKK][BN + 4];

    int bx = blockIdx.x, by = blockIdx.y;
    int tid = threadIdx.x;
    int tx = tid & 15, ty = tid >> 4;

    const float* Ab = A  + (size_t)by * BM * K;
    const float* Bb = Wm + (size_t)bx * BN * K;

    float acc[8][8];
    #pragma unroll
    for (int i = 0; i < 8; i++)
        #pragma unroll
        for (int j = 0; j < 8; j++) acc[i][j] = 0.0f;

    for (int k0 = 0; k0 < K; k0 += BKK) {
        #pragma unroll
        for (int it = 0; it < 2; it++) {
            int v   = tid + it * 256;     // 0..511
            int row = v >> 2;             // 0..127
            int kq  = (v & 3) * 4;        // 0,4,8,12
            float4 av = *(const float4*)(Ab + (size_t)row * K + k0 + kq);
            As[kq+0][row] = av.x; As[kq+1][row] = av.y;
            As[kq+2][row] = av.z; As[kq+3][row] = av.w;
            float4 bv = *(const float4*)(Bb + (size_t)row * K + k0 + kq);
            Bs[kq+0][row] = bv.x; Bs[kq+1][row] = bv.y;
            Bs[kq+2][row] = bv.z; Bs[kq+3][row] = bv.w;
        }
        __syncthreads();
        #pragma unroll
        for (int k = 0; k < BKK; k++) {
            float4 a0 = *(const float4*)&As[k][ty*8];
            float4 a1 = *(const float4*)&As[k][ty*8 + 4];
            float4 b0 = *(const float4*)&Bs[k][tx*8];
            float4 b1 = *(const float4*)&Bs[k][tx*8 + 4];
            float ar[8] = {a0.x,a0.y,a0.z,a0.w,a1.x,a1.y,a1.z,a1.w};
            float br[8] = {b0.x,b0.y,b0.z,b0.w,b1.x,b1.y,b1.z,b1.w};
            #pragma unroll
            for (int i = 0; i < 8; i++)
                #pragma unroll
                for (int j = 0; j < 8; j++)
                    acc[i][j] += ar[i] * br[j];
        }
        __syncthreads();
    }

    int rowg = by * BM + ty * 8;
    int colg = bx * BN + tx * 8;

    if (MODE == 0) {
        #pragma unroll
        for (int i = 0; i < 8; i++) {
            int row = rowg + i;
            #pragma unroll
            for (int j = 0; j < 8; j++) {
                int col = colg + j;
                float v = acc[i][j] + bi[col];
                if (col < 256) {
                    g_q[(size_t)row * C_ + col] = v;
                } else {
                    int o = col - 256;
                    int hh = o >> 6, r = o & 63;
                    if (r < 32) g_k[(size_t)row * C_ + hh*32 + r] = v;
                    else        g_v[(size_t)row * C_ + hh*32 + (r - 32)] = v;
                }
            }
        }
    } else {
        float* dst = (MODE == 1) ? g_x : (MODE == 2) ? g_h1 : outp;
        #pragma unroll
        for (int i = 0; i < 8; i++) {
            size_t base = (size_t)(rowg + i) * Nw + colg;
            #pragma unroll
            for (int j = 0; j < 8; j++) {
                float v = acc[i][j] + bi[colg + j];
                if (MODE == 1) v += resp[base + j];
                if (MODE == 2) v = gelu_exact(v);
                if (MODE == 3) v += g_x[base + j];
                dst[base + j] = v;
            }
        }
    }
}

// ---------------- attention: 1 block per token, 1 warp per head ---------------
__global__ void __launch_bounds__(256) attn_kernel(const int* __restrict__ member_idx,
                                                   const int* __restrict__ pe_idx,
                                                   const float* __restrict__ cmask,
                                                   const float* __restrict__ blank_k,
                                                   const float* __restrict__ blank_v)
{
    int tok  = blockIdx.x;            // 0..16383
    int tid  = threadIdx.x;
    int h    = tid >> 5;
    int lane = tid & 31;
    int b    = tok >> 13;             // N=8192
    int rowbase = b << 13;

    __shared__ int   s_idx[32];
    __shared__ int   s_pe[32];
    __shared__ float s_madd[32];
    if (tid < 32)      s_idx[tid]      = member_idx[(size_t)tok*32 + tid];
    else if (tid < 64) s_pe[tid - 32]  = pe_idx[(size_t)tok*32 + (tid - 32)];
    else if (tid < 96) s_madd[tid - 64] = (1.0f - cmask[(size_t)tok*32 + (tid - 64)]) * -100.0f;
    __syncthreads();

    size_t qoff = (size_t)tok * C_ + h*CH_ + lane;
    float qv = g_q[qoff];

    float vreg[32];
    float myscore = 0.0f;
    #pragma unroll
    for (int m = 0; m < 32; m++) {
        size_t roff = ((size_t)(rowbase + s_idx[m])) * C_ + h*CH_ + lane;
        float kv = g_k[roff];
        vreg[m]  = g_v[roff];
        float d = qv * kv;
        #pragma unroll
        for (int o = 16; o > 0; o >>= 1) d += __shfl_xor_sync(0xffffffffu, d, o);
        if (m == lane) myscore = d;
    }

    myscore += g_pe[s_pe[lane]*H_ + h] + s_madd[lane];

    // blank logit
    float bd = qv * blank_k[h*CH_ + lane];
    #pragma unroll
    for (int o = 16; o > 0; o >>= 1) bd += __shfl_xor_sync(0xffffffffu, bd, o);
    bd = fminf(fmaxf(bd, -5.0f), 5.0f);

    // softmax over 32 members + blank
    float mx = myscore;
    #pragma unroll
    for (int o = 16; o > 0; o >>= 1) mx = fmaxf(mx, __shfl_xor_sync(0xffffffffu, mx, o));
    mx = fmaxf(mx, bd);
    float p  = expf(myscore - mx);
    float pb = expf(bd - mx);
    float ps = p;
    #pragma unroll
    for (int o = 16; o > 0; o >>= 1) ps += __shfl_xor_sync(0xffffffffu, ps, o);
    ps += pb;
    float inv = 1.0f / ps;
    p *= inv;

    float accv = (pb * inv) * blank_v[h*CH_ + lane];
    #pragma unroll
    for (int m = 0; m < 32; m++) {
        float pm = __shfl_sync(0xffffffffu, p, m);
        accv += pm * vreg[m];
    }
    g_ao[qoff] = accv;
}

// ---------------- launch ------------------------------------------------------
extern "C" void kernel_launch(void* const* d_in, const int* in_sizes, int n_in,
                              void* d_out, int out_size)
{
    const float* feat  = (const float*)d_in[0];
    const int*   midx  = (const int*)  d_in[1];
    const float* cmask = (const float*)d_in[2];
    const int*   peidx = (const int*)  d_in[3];
    // d_in[4] = global_attn (unused, always 0)
    const float* pre   = (const float*)d_in[5];
    const float* n1w   = (const float*)d_in[6];
    const float* n1b   = (const float*)d_in[7];
    const float* qw    = (const float*)d_in[8];
    const float* qb    = (const float*)d_in[9];
    const float* kvw   = (const float*)d_in[10];
    const float* kvb   = (const float*)d_in[11];
    const float* bk    = (const float*)d_in[12];
    const float* bv    = (const float*)d_in[13];
    const float* pew   = (const float*)d_in[14];
    const float* peb   = (const float*)d_in[15];
    const float* pjw   = (const float*)d_in[16];
    const float* pjb   = (const float*)d_in[17];
    const float* n2w   = (const float*)d_in[18];
    const float* n2b   = (const float*)d_in[19];
    const float* f1w   = (const float*)d_in[20];
    const float* f1b   = (const float*)d_in[21];
    const float* f2w   = (const float*)d_in[22];
    const float* f2b   = (const float*)d_in[23];
    float* out = (float*)d_out;

    // prep: pack W1/b1 + pe_table
    prep_kernel<<<768, 256>>>(qw, qb, kvw, kvb, pre, pew, peb);

    // LN1: feat -> g_xln
    ln_kernel<0><<<(NTOK*32)/256, 256>>>(feat, n1w, n1b);

    // QKV: g_xln @ g_w1^T -> g_q/g_k/g_v  (M=16384, N=768, K=256)
    sgemm_nt<0><<<dim3(768/BN, NTOK/BM), 256>>>(nullptr, nullptr, nullptr, nullptr, 768, 256);

    // attention -> g_ao
    attn_kernel<<<NTOK, 256>>>(midx, peidx, cmask, bk, bv);

    // proj + residual(feat) -> g_x  (N=256, K=256)
    sgemm_nt<1><<<dim3(256/BN, NTOK/BM), 256>>>(pjw, pjb, feat, nullptr, 256, 256);

    // LN2: g_x -> g_xln2
    ln_kernel<1><<<(NTOK*32)/256, 256>>>(nullptr, n2w, n2b);

    // fc1 + gelu -> g_h1  (N=512, K=256)
    sgemm_nt<2><<<dim3(512/BN, NTOK/BM), 256>>>(f1w, f1b, nullptr, nullptr, 512, 256);

    // fc2 + residual(g_x) -> out  (N=256, K=512)
    sgemm_nt<3><<<dim3(256/BN, NTOK/BM), 256>>>(f2w, f2b, nullptr, out, 256, 512);
}

// round 7
// speedup vs baseline: 1.9542x; 1.9542x over previous
#include <cuda_runtime.h>
#include <cuda_bf16.h>
#include <math.h>
#include <stdint.h>

#define NTOK 16384
#define C_ 256
#define H_ 8
#define TAB_ 3025

// ---- device scratch (no allocation allowed) ----
// g_wpack rows are [hi(K)|lo(K)] bf16. offsets: qkv 0, proj 393216, fc1 524288, fc2 786432
__device__ __align__(256) __nv_bfloat16 g_wpack[1048576];
__device__ float g_bqkv[768];
__device__ float g_pe[TAB_ * H_];
__device__ __align__(256) __nv_bfloat16 g_a1[NTOK * 512];
__device__ __align__(256) __nv_bfloat16 g_a2[NTOK * 512];
__device__ __align__(256) __nv_bfloat16 g_ao[NTOK * 512];
__device__ __align__(256) __nv_bfloat16 g_h1[NTOK * 1024];
__device__ __align__(256) float g_q[NTOK * C_];
__device__ __align__(256) float g_k[NTOK * C_];
__device__ __align__(256) float g_v[NTOK * C_];
__device__ __align__(256) float g_x[NTOK * C_];

// ---- PTX helpers (sm_80-compatible only; NO tcgen05) ----
__device__ __forceinline__ uint32_t smem_u32(const void* p) {
    uint32_t a;
    asm("{ .reg .u64 t; cvta.to.shared.u64 t, %1; cvt.u32.u64 %0, t; }" : "=r"(a) : "l"(p));
    return a;
}
#define CP_ASYNC16(d, s) asm volatile("cp.async.cg.shared.global [%0], [%1], 16;" :: "r"(d), "l"(s) : "memory")
#define CP_COMMIT()      asm volatile("cp.async.commit_group;" ::: "memory")
#define CP_WAIT0()       asm volatile("cp.async.wait_group 0;" ::: "memory")
#define CP_WAIT1()       asm volatile("cp.async.wait_group 1;" ::: "memory")
#define LDSM4(r0, r1, r2, r3, addr) \
    asm volatile("ldmatrix.sync.aligned.m8n8.x4.shared.b16 {%0,%1,%2,%3}, [%4];" \
        : "=r"(r0), "=r"(r1), "=r"(r2), "=r"(r3) : "r"(addr))
#define MMA16816(d, a, b) \
    asm volatile("mma.sync.aligned.m16n8k16.row.col.f32.bf16.bf16.f32 " \
        "{%0,%1,%2,%3},{%4,%5,%6,%7},{%8,%9},{%0,%1,%2,%3};" \
        : "+f"((d)[0]), "+f"((d)[1]), "+f"((d)[2]), "+f"((d)[3]) \
        : "r"((a)[0]), "r"((a)[1]), "r"((a)[2]), "r"((a)[3]), "r"((b)[0]), "r"((b)[1]))

__device__ __forceinline__ float gelu_exact(float v) { return 0.5f * v * (1.0f + erff(v * 0.70710678118654752f)); }

// ---- prep ----
__global__ void pack_w_kernel(const float* __restrict__ src, int nelem, int K, int dstoff, float scale)
{
    int i = blockIdx.x * blockDim.x + threadIdx.x;
    if (i >= nelem) return;
    int row = i / K, col = i - row * K;
    float v = src[i] * scale;
    __nv_bfloat16 hi = __float2bfloat16(v);
    __nv_bfloat16 lo = __float2bfloat16(v - __bfloat162float(hi));
    size_t base = (size_t)dstoff + (size_t)row * (2 * K);
    g_wpack[base + col] = hi;
    g_wpack[base + K + col] = lo;
}

__global__ void prep_misc_kernel(const float* __restrict__ qb, const float* __restrict__ kvb,
                                 const float* __restrict__ pre, const float* __restrict__ pew,
                                 const float* __restrict__ peb)
{
    const float scale = 0.17677669529663687f;
    int t = blockIdx.x * blockDim.x + threadIdx.x;
    if (t < 768) g_bqkv[t] = (t < 256) ? qb[t] * scale : kvb[t - 256];
    if (t < TAB_ * H_) {
        int tab = t >> 3, h = t & 7;
        float s = peb[h];
        #pragma unroll
        for (int f = 0; f < 5; f++) s += pre[tab * 5 + f] * pew[h * 5 + f];
        g_pe[t] = s;
    }
}

// ---- LayerNorm -> packed hi|lo bf16 ----
template<int WHICH>
__global__ void ln_kernel(const float* __restrict__ xin,
                          const float* __restrict__ w, const float* __restrict__ b)
{
    int gw = (blockIdx.x * blockDim.x + threadIdx.x) >> 5;
    int lane = threadIdx.x & 31;
    if (gw >= NTOK) return;
    const float* src = (WHICH == 0) ? xin : g_x;
    __nv_bfloat16* dst = (WHICH == 0) ? g_a1 : g_a2;
    const float4* xr = (const float4*)(src + (size_t)gw * C_);
    float4 a = xr[lane * 2], c = xr[lane * 2 + 1];
    float s  = a.x + a.y + a.z + a.w + c.x + c.y + c.z + c.w;
    float ss = a.x*a.x + a.y*a.y + a.z*a.z + a.w*a.w + c.x*c.x + c.y*c.y + c.z*c.z + c.w*c.w;
    #pragma unroll
    for (int o = 16; o > 0; o >>= 1) {
        s  += __shfl_xor_sync(0xffffffffu, s, o);
        ss += __shfl_xor_sync(0xffffffffu, ss, o);
    }
    float mean = s * (1.0f / 256.0f);
    float rstd = rsqrtf(ss * (1.0f / 256.0f) - mean * mean + 1e-5f);
    int c0 = lane * 8;
    float vals[8] = {a.x, a.y, a.z, a.w, c.x, c.y, c.z, c.w};
    __nv_bfloat16 hi[8], lo[8];
    #pragma unroll
    for (int j = 0; j < 8; j++) {
        float v = (vals[j] - mean) * rstd * w[c0 + j] + b[c0 + j];
        hi[j] = __float2bfloat16(v);
        lo[j] = __float2bfloat16(v - __bfloat162float(hi[j]));
    }
    *(uint4*)(dst + (size_t)gw * 512 + c0)       = *(uint4*)hi;
    *(uint4*)(dst + (size_t)gw * 512 + 256 + c0) = *(uint4*)lo;
}

// ---- bf16 HMMA GEMM: block 128x128, warp 32x64, K-chunks of 64, K' = 3K hi/lo ----
// smem: A buf0 16K | A buf1 16K | B buf0 16K | B buf1 16K = 65536 B
#define SMEM_BYTES 65536

template<int KP>
__device__ __forceinline__ void load_chunk(uint32_t sbase, const __nv_bfloat16* Ab,
                                           const __nv_bfloat16* Wb, int c, int tid)
{
    int k0p = c * 64, seg = k0p / KP, kk = k0p % KP;
    const __nv_bfloat16* As = Ab + ((seg == 1) ? KP : 0) + kk;  // A: [hi, lo, hi]
    const __nv_bfloat16* Ws = Wb + ((seg == 2) ? KP : 0) + kk;  // W: [hi, hi, lo]
    uint32_t abuf = sbase + (c & 1) * 16384;
    uint32_t bbuf = sbase + 32768 + (c & 1) * 16384;
    #pragma unroll
    for (int it = 0; it < 4; it++) {
        int i = tid + it * 256, row = i >> 3, c8 = i & 7;
        uint32_t sw = row * 128 + ((c8 * 16) ^ ((row & 7) << 4));
        CP_ASYNC16(abuf + sw, As + (size_t)row * (2 * KP) + c8 * 8);
        CP_ASYNC16(bbuf + sw, Ws + (size_t)row * (2 * KP) + c8 * 8);
    }
    CP_COMMIT();
}

template<int MODE>
__global__ void __launch_bounds__(256, 2) mm_kernel(const float* __restrict__ biasp,
                                                    const float* __restrict__ resp,
                                                    float* __restrict__ outp)
{
    constexpr int KP = (MODE == 3) ? 512 : 256;
    constexpr int NC = 3 * KP / 64;
    constexpr int WOFF = (MODE == 0) ? 0 : (MODE == 1) ? 393216 : (MODE == 2) ? 524288 : 786432;

    extern __shared__ char dsm[];
    uint32_t sbase = smem_u32(dsm);
    int tid = threadIdx.x, wid = tid >> 5, lane = tid & 31;
    int bx = blockIdx.x, by = blockIdx.y;

    const __nv_bfloat16* Ag = (MODE == 0) ? g_a1 : (MODE == 1) ? g_ao : (MODE == 2) ? g_a2 : g_h1;
    const __nv_bfloat16* Ab = Ag + (size_t)by * 128 * (2 * KP);
    const __nv_bfloat16* Wb = g_wpack + WOFF + (size_t)bx * 128 * (2 * KP);

    float acc[2][8][4];
    #pragma unroll
    for (int i = 0; i < 2; i++)
        #pragma unroll
        for (int j = 0; j < 8; j++)
            #pragma unroll
            for (int q = 0; q < 4; q++) acc[i][j][q] = 0.0f;

    int m0 = (wid & 3) * 32, n0 = (wid >> 2) * 64;
    int rA = lane & 15,                      kA = (lane >> 4) * 16;
    int rB = (lane & 7) + ((lane >> 4) << 3), kB = ((lane >> 3) & 1) * 16;

    load_chunk<KP>(sbase, Ab, Wb, 0, tid);

    #pragma unroll 1
    for (int c = 0; c < NC; c++) {
        if (c + 1 < NC) { load_chunk<KP>(sbase, Ab, Wb, c + 1, tid); CP_WAIT1(); }
        else CP_WAIT0();
        __syncthreads();
        uint32_t abuf = sbase + (c & 1) * 16384;
        uint32_t bbuf = sbase + 32768 + (c & 1) * 16384;
        #pragma unroll
        for (int ks = 0; ks < 4; ks++) {
            uint32_t a[2][4];
            #pragma unroll
            for (int i = 0; i < 2; i++) {
                int r = m0 + i * 16 + rA;
                int kb = ks * 32 + kA;
                LDSM4(a[i][0], a[i][1], a[i][2], a[i][3],
                      abuf + r * 128 + (kb ^ ((r & 7) << 4)));
            }
            uint32_t b[8][2];
            #pragma unroll
            for (int jj = 0; jj < 4; jj++) {
                int r = n0 + jj * 16 + rB;
                int kb = ks * 32 + kB;
                LDSM4(b[jj*2][0], b[jj*2][1], b[jj*2+1][0], b[jj*2+1][1],
                      bbuf + r * 128 + (kb ^ ((r & 7) << 4)));
            }
            #pragma unroll
            for (int i = 0; i < 2; i++)
                #pragma unroll
                for (int j = 0; j < 8; j++)
                    MMA16816(acc[i][j], a[i], b[j]);
        }
        __syncthreads();
    }

    // epilogue: d0,d1 = row l/4, cols (l%4)*2,+1; d2,d3 = row l/4+8
    int row_l = lane >> 2, col_l = (lane & 3) * 2;
    #pragma unroll
    for (int i = 0; i < 2; i++)
        #pragma unroll
        for (int j = 0; j < 8; j++)
            #pragma unroll
            for (int h = 0; h < 2; h++) {
                int row = by * 128 + m0 + i * 16 + h * 8 + row_l;
                int gc  = bx * 128 + n0 + j * 8 + col_l;
                float v0 = acc[i][j][h * 2], v1 = acc[i][j][h * 2 + 1];
                if (MODE == 0) {
                    v0 += g_bqkv[gc]; v1 += g_bqkv[gc + 1];
                    float* dst; int dc;
                    if (gc < 256) { dst = g_q; dc = gc; }
                    else {
                        int o = gc - 256;
                        dst = ((o & 63) < 32) ? g_k : g_v;
                        dc = (o >> 6) * 32 + (o & 31);
                    }
                    *(float2*)(dst + (size_t)row * 256 + dc) = make_float2(v0, v1);
                } else if (MODE == 1) {
                    size_t base = (size_t)row * 256 + gc;
                    v0 += biasp[gc] + resp[base];
                    v1 += biasp[gc + 1] + resp[base + 1];
                    *(float2*)(g_x + base) = make_float2(v0, v1);
                } else if (MODE == 2) {
                    v0 = gelu_exact(v0 + biasp[gc]);
                    v1 = gelu_exact(v1 + biasp[gc + 1]);
                    __nv_bfloat16 h0 = __float2bfloat16(v0), h1 = __float2bfloat16(v1);
                    __nv_bfloat162 hp; hp.x = h0; hp.y = h1;
                    __nv_bfloat162 lp;
                    lp.x = __float2bfloat16(v0 - __bfloat162float(h0));
                    lp.y = __float2bfloat16(v1 - __bfloat162float(h1));
                    size_t base = (size_t)row * 1024 + gc;
                    *(__nv_bfloat162*)(g_h1 + base)       = hp;
                    *(__nv_bfloat162*)(g_h1 + base + 512) = lp;
                } else {
                    size_t base = (size_t)row * 256 + gc;
                    v0 += biasp[gc] + g_x[base];
                    v1 += biasp[gc + 1] + g_x[base + 1];
                    *(float2*)(outp + base) = make_float2(v0, v1);
                }
            }
}

// ---- attention: 1 block/token, 1 warp/head, butterfly multi-reduce ----
__global__ void __launch_bounds__(256) attn_kernel(const int* __restrict__ member_idx,
                                                   const int* __restrict__ pe_idx,
                                                   const float* __restrict__ cmask,
                                                   const float* __restrict__ blank_k,
                                                   const float* __restrict__ blank_v)
{
    int tok = blockIdx.x, tid = threadIdx.x;
    int h = tid >> 5, lane = tid & 31;
    int rowbase = (tok >> 13) << 13;

    __shared__ int s_idx[32];
    __shared__ int s_pe[32];
    __shared__ float s_madd[32];
    if (tid < 32)      s_idx[tid] = member_idx[(size_t)tok * 32 + tid];
    else if (tid < 64) s_pe[tid - 32] = pe_idx[(size_t)tok * 32 + (tid - 32)];
    else if (tid < 96) s_madd[tid - 64] = (1.0f - cmask[(size_t)tok * 32 + (tid - 64)]) * -100.0f;
    __syncthreads();

    int ch = h * 32 + lane;
    float qv = g_q[(size_t)tok * C_ + ch];

    float d[32];
    #pragma unroll
    for (int m = 0; m < 32; m++)
        d[m] = qv * g_k[(size_t)(rowbase + s_idx[m]) * C_ + ch];

    // butterfly transpose-reduce: lane ends with full score for member == lane
    int nv = 32;
    #pragma unroll
    for (int o = 16; o > 0; o >>= 1) {
        nv >>= 1;
        bool up = lane & o;
        #pragma unroll
        for (int j = 0; j < 16; j++) {
            if (j >= nv) break;
            float sent = up ? d[j] : d[j + nv];
            float got = __shfl_xor_sync(0xffffffffu, sent, o);
            d[j] = (up ? d[j + nv] : d[j]) + got;
        }
    }
    float sc = d[0] + g_pe[s_pe[lane] * H_ + h] + s_madd[lane];

    float bd = qv * blank_k[ch];
    #pragma unroll
    for (int o = 16; o > 0; o >>= 1) bd += __shfl_xor_sync(0xffffffffu, bd, o);
    bd = fminf(fmaxf(bd, -5.0f), 5.0f);

    float mx = sc;
    #pragma unroll
    for (int o = 16; o > 0; o >>= 1) mx = fmaxf(mx, __shfl_xor_sync(0xffffffffu, mx, o));
    mx = fmaxf(mx, bd);
    float p = expf(sc - mx), pb = expf(bd - mx);
    float ps = p;
    #pragma unroll
    for (int o = 16; o > 0; o >>= 1) ps += __shfl_xor_sync(0xffffffffu, ps, o);
    float inv = 1.0f / (ps + pb);
    p *= inv;

    float acc = (pb * inv) * blank_v[ch];
    #pragma unroll
    for (int m = 0; m < 32; m++) {
        float pm = __shfl_sync(0xffffffffu, p, m);
        acc += pm * g_v[(size_t)(rowbase + s_idx[m]) * C_ + ch];
    }

    __nv_bfloat16 hi = __float2bfloat16(acc);
    __nv_bfloat16 lo = __float2bfloat16(acc - __bfloat162float(hi));
    g_ao[(size_t)tok * 512 + ch] = hi;
    g_ao[(size_t)tok * 512 + 256 + ch] = lo;
}

// ---- launch ----
extern "C" void kernel_launch(void* const* d_in, const int* in_sizes, int n_in,
                              void* d_out, int out_size)
{
    const float* feat  = (const float*)d_in[0];
    const int*   midx  = (const int*)  d_in[1];
    const float* cmask = (const float*)d_in[2];
    const int*   peidx = (const int*)  d_in[3];
    const float* pre   = (const float*)d_in[5];
    const float* n1w   = (const float*)d_in[6];
    const float* n1b   = (const float*)d_in[7];
    const float* qw    = (const float*)d_in[8];
    const float* qb    = (const float*)d_in[9];
    const float* kvw   = (const float*)d_in[10];
    const float* kvb   = (const float*)d_in[11];
    const float* bk    = (const float*)d_in[12];
    const float* bv    = (const float*)d_in[13];
    const float* pew   = (const float*)d_in[14];
    const float* peb   = (const float*)d_in[15];
    const float* pjw   = (const float*)d_in[16];
    const float* pjb   = (const float*)d_in[17];
    const float* n2w   = (const float*)d_in[18];
    const float* n2b   = (const float*)d_in[19];
    const float* f1w   = (const float*)d_in[20];
    const float* f1b   = (const float*)d_in[21];
    const float* f2w   = (const float*)d_in[22];
    const float* f2b   = (const float*)d_in[23];
    float* out = (float*)d_out;

    cudaFuncSetAttribute(mm_kernel<0>, cudaFuncAttributeMaxDynamicSharedMemorySize, SMEM_BYTES);
    cudaFuncSetAttribute(mm_kernel<1>, cudaFuncAttributeMaxDynamicSharedMemorySize, SMEM_BYTES);
    cudaFuncSetAttribute(mm_kernel<2>, cudaFuncAttributeMaxDynamicSharedMemorySize, SMEM_BYTES);
    cudaFuncSetAttribute(mm_kernel<3>, cudaFuncAttributeMaxDynamicSharedMemorySize, SMEM_BYTES);

    const float scale = 0.17677669529663687f;
    pack_w_kernel<<<256, 256>>>(qw, 65536, 256, 0, scale);
    pack_w_kernel<<<512, 256>>>(kvw, 131072, 256, 131072, 1.0f);
    pack_w_kernel<<<256, 256>>>(pjw, 65536, 256, 393216, 1.0f);
    pack_w_kernel<<<512, 256>>>(f1w, 131072, 256, 524288, 1.0f);
    pack_w_kernel<<<512, 256>>>(f2w, 131072, 512, 786432, 1.0f);
    prep_misc_kernel<<<95, 256>>>(qb, kvb, pre, pew, peb);

    ln_kernel<0><<<(NTOK * 32) / 256, 256>>>(feat, n1w, n1b);
    mm_kernel<0><<<dim3(6, 128), 256, SMEM_BYTES>>>(nullptr, nullptr, nullptr);
    attn_kernel<<<NTOK, 256>>>(midx, peidx, cmask, bk, bv);
    mm_kernel<1><<<dim3(2, 128), 256, SMEM_BYTES>>>(pjb, feat, nullptr);
    ln_kernel<1><<<(NTOK * 32) / 256, 256>>>(nullptr, n2w, n2b);
    mm_kernel<2><<<dim3(4, 128), 256, SMEM_BYTES>>>(f1b, nullptr, nullptr);
    mm_kernel<3><<<dim3(2, 128), 256, SMEM_BYTES>>>(f2b, nullptr, out);
}

// round 15
// speedup vs baseline: 2.0115x; 1.0293x over previous
#include <cuda_runtime.h>
#include <cuda_bf16.h>
#include <math.h>
#include <stdint.h>

#define NTOK 16384
#define C_ 256
#define H_ 8
#define TAB_ 3025

// ---- device scratch (no allocation allowed) ----
// g_wpack rows are [hi(K)|lo(K)] bf16. offsets: qkv 0, proj 393216, fc1 524288, fc2 786432
__device__ __align__(256) __nv_bfloat16 g_wpack[1048576];
__device__ float g_bqkv[768];
__device__ float g_pe[TAB_ * H_];
__device__ __align__(256) __nv_bfloat16 g_a1[NTOK * 512];
__device__ __align__(256) __nv_bfloat16 g_a2[NTOK * 512];
__device__ __align__(256) __nv_bfloat16 g_ao[NTOK * 512];
__device__ __align__(256) __nv_bfloat16 g_h1[NTOK * 1024];
__device__ __align__(256) float g_q[NTOK * C_];
__device__ __align__(256) float g_k[NTOK * C_];
__device__ __align__(256) float g_v[NTOK * C_];
__device__ __align__(256) float g_x[NTOK * C_];

// ---- PTX helpers (sm_80-compatible only; NO tcgen05) ----
__device__ __forceinline__ uint32_t smem_u32(const void* p) {
    uint32_t a;
    asm("{ .reg .u64 t; cvta.to.shared.u64 t, %1; cvt.u32.u64 %0, t; }" : "=r"(a) : "l"(p));
    return a;
}
#define CP_ASYNC16(d, s) asm volatile("cp.async.cg.shared.global [%0], [%1], 16;" :: "r"(d), "l"(s) : "memory")
#define CP_COMMIT()      asm volatile("cp.async.commit_group;" ::: "memory")
#define CP_WAIT0()       asm volatile("cp.async.wait_group 0;" ::: "memory")
#define CP_WAIT1()       asm volatile("cp.async.wait_group 1;" ::: "memory")
#define LDSM4(r0, r1, r2, r3, addr) \
    asm volatile("ldmatrix.sync.aligned.m8n8.x4.shared.b16 {%0,%1,%2,%3}, [%4];" \
        : "=r"(r0), "=r"(r1), "=r"(r2), "=r"(r3) : "r"(addr))
#define MMA16816(d, a, b) \
    asm volatile("mma.sync.aligned.m16n8k16.row.col.f32.bf16.bf16.f32 " \
        "{%0,%1,%2,%3},{%4,%5,%6,%7},{%8,%9},{%0,%1,%2,%3};" \
        : "+f"((d)[0]), "+f"((d)[1]), "+f"((d)[2]), "+f"((d)[3]) \
        : "r"((a)[0]), "r"((a)[1]), "r"((a)[2]), "r"((a)[3]), "r"((b)[0]), "r"((b)[1]))

__device__ __forceinline__ float gelu_exact(float v) { return 0.5f * v * (1.0f + erff(v * 0.70710678118654752f)); }

// ---- fused prologue: LN1 (blocks 0..2047) + weight pack (2048..4095) + bias/pe (4096..4193) ----
// pack total = 65536 + 131072 + 65536 + 131072 + 131072 = 524288 elements = 2048 blocks
#define LN_BLOCKS   2048
#define PACK_BLOCKS 2048
#define MISC_BLOCKS 98
#define PROLOGUE_GRID (LN_BLOCKS + PACK_BLOCKS + MISC_BLOCKS)

__global__ void __launch_bounds__(256) prologue_kernel(
    const float* __restrict__ feat, const float* __restrict__ n1w, const float* __restrict__ n1b,
    const float* __restrict__ qw, const float* __restrict__ kvw, const float* __restrict__ pjw,
    const float* __restrict__ f1w, const float* __restrict__ f2w,
    const float* __restrict__ qb, const float* __restrict__ kvb,
    const float* __restrict__ pre, const float* __restrict__ pew, const float* __restrict__ peb)
{
    const float qscale = 0.17677669529663687f; // 32^-0.5
    int blk = blockIdx.x;
    if (blk < LN_BLOCKS) {
        // LN1: one warp per token
        int gw = blk * 8 + (threadIdx.x >> 5);
        int lane = threadIdx.x & 31;
        const float4* xr = (const float4*)(feat + (size_t)gw * C_);
        float4 a = xr[lane * 2], c = xr[lane * 2 + 1];
        float s  = a.x + a.y + a.z + a.w + c.x + c.y + c.z + c.w;
        float ss = a.x*a.x + a.y*a.y + a.z*a.z + a.w*a.w + c.x*c.x + c.y*c.y + c.z*c.z + c.w*c.w;
        #pragma unroll
        for (int o = 16; o > 0; o >>= 1) {
            s  += __shfl_xor_sync(0xffffffffu, s, o);
            ss += __shfl_xor_sync(0xffffffffu, ss, o);
        }
        float mean = s * (1.0f / 256.0f);
        float rstd = rsqrtf(ss * (1.0f / 256.0f) - mean * mean + 1e-5f);
        int c0 = lane * 8;
        float vals[8] = {a.x, a.y, a.z, a.w, c.x, c.y, c.z, c.w};
        __nv_bfloat16 hi[8], lo[8];
        #pragma unroll
        for (int j = 0; j < 8; j++) {
            float v = (vals[j] - mean) * rstd * n1w[c0 + j] + n1b[c0 + j];
            hi[j] = __float2bfloat16(v);
            lo[j] = __float2bfloat16(v - __bfloat162float(hi[j]));
        }
        *(uint4*)(g_a1 + (size_t)gw * 512 + c0)       = *(uint4*)hi;
        *(uint4*)(g_a1 + (size_t)gw * 512 + 256 + c0) = *(uint4*)lo;
    } else if (blk < LN_BLOCKS + PACK_BLOCKS) {
        int i = (blk - LN_BLOCKS) * 256 + threadIdx.x;  // 0..524287
        const float* src; int K, dstoff, si; float scale = 1.0f;
        if (i < 65536)       { src = qw;  K = 256; dstoff = 0;      si = i;          scale = qscale; }
        else if (i < 196608) { src = kvw; K = 256; dstoff = 131072; si = i - 65536;  }
        else if (i < 262144) { src = pjw; K = 256; dstoff = 393216; si = i - 196608; }
        else if (i < 393216) { src = f1w; K = 256; dstoff = 524288; si = i - 262144; }
        else                 { src = f2w; K = 512; dstoff = 786432; si = i - 393216; }
        int row = si / K, col = si - row * K;
        float v = src[si] * scale;
        __nv_bfloat16 hi = __float2bfloat16(v);
        __nv_bfloat16 lo = __float2bfloat16(v - __bfloat162float(hi));
        size_t base = (size_t)dstoff + (size_t)row * (2 * K);
        g_wpack[base + col] = hi;
        g_wpack[base + K + col] = lo;
    } else {
        int t = (blk - LN_BLOCKS - PACK_BLOCKS) * 256 + threadIdx.x;
        if (t < 768) g_bqkv[t] = (t < 256) ? qb[t] * qscale : kvb[t - 256];
        else if (t < 768 + TAB_ * H_) {
            int u = t - 768;
            int tab = u >> 3, h = u & 7;
            float s = peb[h];
            #pragma unroll
            for (int f = 0; f < 5; f++) s += pre[tab * 5 + f] * pew[h * 5 + f];
            g_pe[u] = s;
        }
    }
}

// ---- LayerNorm 2: g_x -> packed hi|lo bf16 in g_a2 ----
__global__ void ln2_kernel(const float* __restrict__ w, const float* __restrict__ b)
{
    int gw = (blockIdx.x * blockDim.x + threadIdx.x) >> 5;
    int lane = threadIdx.x & 31;
    if (gw >= NTOK) return;
    const float4* xr = (const float4*)(g_x + (size_t)gw * C_);
    float4 a = xr[lane * 2], c = xr[lane * 2 + 1];
    float s  = a.x + a.y + a.z + a.w + c.x + c.y + c.z + c.w;
    float ss = a.x*a.x + a.y*a.y + a.z*a.z + a.w*a.w + c.x*c.x + c.y*c.y + c.z*c.z + c.w*c.w;
    #pragma unroll
    for (int o = 16; o > 0; o >>= 1) {
        s  += __shfl_xor_sync(0xffffffffu, s, o);
        ss += __shfl_xor_sync(0xffffffffu, ss, o);
    }
    float mean = s * (1.0f / 256.0f);
    float rstd = rsqrtf(ss * (1.0f / 256.0f) - mean * mean + 1e-5f);
    int c0 = lane * 8;
    float vals[8] = {a.x, a.y, a.z, a.w, c.x, c.y, c.z, c.w};
    __nv_bfloat16 hi[8], lo[8];
    #pragma unroll
    for (int j = 0; j < 8; j++) {
        float v = (vals[j] - mean) * rstd * w[c0 + j] + b[c0 + j];
        hi[j] = __float2bfloat16(v);
        lo[j] = __float2bfloat16(v - __bfloat162float(hi[j]));
    }
    *(uint4*)(g_a2 + (size_t)gw * 512 + c0)       = *(uint4*)hi;
    *(uint4*)(g_a2 + (size_t)gw * 512 + 256 + c0) = *(uint4*)lo;
}

// ---- bf16 HMMA GEMM: block 128x128, warp 32x64, K-chunks of 64, K' = 3K hi/lo ----
// smem: A buf0 16K | A buf1 16K | B buf0 16K | B buf1 16K = 65536 B
#define SMEM_BYTES 65536

template<int KP>
__device__ __forceinline__ void load_chunk(uint32_t sbase, const __nv_bfloat16* Ab,
                                           const __nv_bfloat16* Wb, int c, int tid)
{
    int k0p = c * 64, seg = k0p / KP, kk = k0p % KP;
    const __nv_bfloat16* As = Ab + ((seg == 1) ? KP : 0) + kk;  // A: [hi, lo, hi]
    const __nv_bfloat16* Ws = Wb + ((seg == 2) ? KP : 0) + kk;  // W: [hi, hi, lo]
    uint32_t abuf = sbase + (c & 1) * 16384;
    uint32_t bbuf = sbase + 32768 + (c & 1) * 16384;
    #pragma unroll
    for (int it = 0; it < 4; it++) {
        int i = tid + it * 256, row = i >> 3, c8 = i & 7;
        uint32_t sw = row * 128 + ((c8 * 16) ^ ((row & 7) << 4));
        CP_ASYNC16(abuf + sw, As + (size_t)row * (2 * KP) + c8 * 8);
        CP_ASYNC16(bbuf + sw, Ws + (size_t)row * (2 * KP) + c8 * 8);
    }
    CP_COMMIT();
}

template<int MODE>
__global__ void __launch_bounds__(256, 2) mm_kernel(const float* __restrict__ biasp,
                                                    const float* __restrict__ resp,
                                                    float* __restrict__ outp)
{
    constexpr int KP = (MODE == 3) ? 512 : 256;
    constexpr int NC = 3 * KP / 64;
    constexpr int WOFF = (MODE == 0) ? 0 : (MODE == 1) ? 393216 : (MODE == 2) ? 524288 : 786432;

    extern __shared__ char dsm[];
    uint32_t sbase = smem_u32(dsm);
    int tid = threadIdx.x, wid = tid >> 5, lane = tid & 31;
    int bx = blockIdx.x, by = blockIdx.y;

    const __nv_bfloat16* Ag = (MODE == 0) ? g_a1 : (MODE == 1) ? g_ao : (MODE == 2) ? g_a2 : g_h1;
    const __nv_bfloat16* Ab = Ag + (size_t)by * 128 * (2 * KP);
    const __nv_bfloat16* Wb = g_wpack + WOFF + (size_t)bx * 128 * (2 * KP);

    float acc[2][8][4];
    #pragma unroll
    for (int i = 0; i < 2; i++)
        #pragma unroll
        for (int j = 0; j < 8; j++)
            #pragma unroll
            for (int q = 0; q < 4; q++) acc[i][j][q] = 0.0f;

    int m0 = (wid & 3) * 32, n0 = (wid >> 2) * 64;
    int rA = lane & 15,                      kA = (lane >> 4) * 16;
    int rB = (lane & 7) + ((lane >> 4) << 3), kB = ((lane >> 3) & 1) * 16;

    load_chunk<KP>(sbase, Ab, Wb, 0, tid);

    #pragma unroll 1
    for (int c = 0; c < NC; c++) {
        if (c + 1 < NC) { load_chunk<KP>(sbase, Ab, Wb, c + 1, tid); CP_WAIT1(); }
        else CP_WAIT0();
        __syncthreads();
        uint32_t abuf = sbase + (c & 1) * 16384;
        uint32_t bbuf = sbase + 32768 + (c & 1) * 16384;
        #pragma unroll
        for (int ks = 0; ks < 4; ks++) {
            uint32_t a[2][4];
            #pragma unroll
            for (int i = 0; i < 2; i++) {
                int r = m0 + i * 16 + rA;
                int kb = ks * 32 + kA;
                LDSM4(a[i][0], a[i][1], a[i][2], a[i][3],
                      abuf + r * 128 + (kb ^ ((r & 7) << 4)));
            }
            uint32_t b[8][2];
            #pragma unroll
            for (int jj = 0; jj < 4; jj++) {
                int r = n0 + jj * 16 + rB;
                int kb = ks * 32 + kB;
                LDSM4(b[jj*2][0], b[jj*2][1], b[jj*2+1][0], b[jj*2+1][1],
                      bbuf + r * 128 + (kb ^ ((r & 7) << 4)));
            }
            #pragma unroll
            for (int i = 0; i < 2; i++)
                #pragma unroll
                for (int j = 0; j < 8; j++)
                    MMA16816(acc[i][j], a[i], b[j]);
        }
        __syncthreads();
    }

    // epilogue: d0,d1 = row l/4, cols (l%4)*2,+1; d2,d3 = row l/4+8
    int row_l = lane >> 2, col_l = (lane & 3) * 2;
    #pragma unroll
    for (int i = 0; i < 2; i++)
        #pragma unroll
        for (int j = 0; j < 8; j++)
            #pragma unroll
            for (int h = 0; h < 2; h++) {
                int row = by * 128 + m0 + i * 16 + h * 8 + row_l;
                int gc  = bx * 128 + n0 + j * 8 + col_l;
                float v0 = acc[i][j][h * 2], v1 = acc[i][j][h * 2 + 1];
                if (MODE == 0) {
                    v0 += g_bqkv[gc]; v1 += g_bqkv[gc + 1];
                    float* dst; int dc;
                    if (gc < 256) { dst = g_q; dc = gc; }
                    else {
                        int o = gc - 256;
                        dst = ((o & 63) < 32) ? g_k : g_v;
                        dc = (o >> 6) * 32 + (o & 31);
                    }
                    *(float2*)(dst + (size_t)row * 256 + dc) = make_float2(v0, v1);
                } else if (MODE == 1) {
                    size_t base = (size_t)row * 256 + gc;
                    v0 += biasp[gc] + resp[base];
                    v1 += biasp[gc + 1] + resp[base + 1];
                    *(float2*)(g_x + base) = make_float2(v0, v1);
                } else if (MODE == 2) {
                    v0 = gelu_exact(v0 + biasp[gc]);
                    v1 = gelu_exact(v1 + biasp[gc + 1]);
                    __nv_bfloat16 h0 = __float2bfloat16(v0), h1 = __float2bfloat16(v1);
                    __nv_bfloat162 hp; hp.x = h0; hp.y = h1;
                    __nv_bfloat162 lp;
                    lp.x = __float2bfloat16(v0 - __bfloat162float(h0));
                    lp.y = __float2bfloat16(v1 - __bfloat162float(h1));
                    size_t base = (size_t)row * 1024 + gc;
                    *(__nv_bfloat162*)(g_h1 + base)       = hp;
                    *(__nv_bfloat162*)(g_h1 + base + 512) = lp;
                } else {
                    size_t base = (size_t)row * 256 + gc;
                    v0 += biasp[gc] + g_x[base];
                    v1 += biasp[gc + 1] + g_x[base + 1];
                    *(float2*)(outp + base) = make_float2(v0, v1);
                }
            }
}

// ---- attention: 1 block/token, 1 warp/head, butterfly multi-reduce ----
__global__ void __launch_bounds__(256) attn_kernel(const int* __restrict__ member_idx,
                                                   const int* __restrict__ pe_idx,
                                                   const float* __restrict__ cmask,
                                                   const float* __restrict__ blank_k,
                                                   const float* __restrict__ blank_v)
{
    int tok = blockIdx.x, tid = threadIdx.x;
    int h = tid >> 5, lane = tid & 31;
    int rowbase = (tok >> 13) << 13;

    __shared__ int s_idx[32];
    __shared__ int s_pe[32];
    __shared__ float s_madd[32];
    if (tid < 32)      s_idx[tid] = member_idx[(size_t)tok * 32 + tid];
    else if (tid < 64) s_pe[tid - 32] = pe_idx[(size_t)tok * 32 + (tid - 32)];
    else if (tid < 96) s_madd[tid - 64] = (1.0f - cmask[(size_t)tok * 32 + (tid - 64)]) * -100.0f;
    __syncthreads();

    int ch = h * 32 + lane;
    float qv = g_q[(size_t)tok * C_ + ch];

    float d[32];
    #pragma unroll
    for (int m = 0; m < 32; m++)
        d[m] = qv * g_k[(size_t)(rowbase + s_idx[m]) * C_ + ch];

    // butterfly transpose-reduce: lane ends with full score for member == lane
    int nv = 32;
    #pragma unroll
    for (int o = 16; o > 0; o >>= 1) {
        nv >>= 1;
        bool up = lane & o;
        #pragma unroll
        for (int j = 0; j < 16; j++) {
            if (j >= nv) break;
            float sent = up ? d[j] : d[j + nv];
            float got = __shfl_xor_sync(0xffffffffu, sent, o);
            d[j] = (up ? d[j + nv] : d[j]) + got;
        }
    }
    float sc = d[0] + g_pe[s_pe[lane] * H_ + h] + s_madd[lane];

    float bd = qv * blank_k[ch];
    #pragma unroll
    for (int o = 16; o > 0; o >>= 1) bd += __shfl_xor_sync(0xffffffffu, bd, o);
    bd = fminf(fmaxf(bd, -5.0f), 5.0f);

    float mx = sc;
    #pragma unroll
    for (int o = 16; o > 0; o >>= 1) mx = fmaxf(mx, __shfl_xor_sync(0xffffffffu, mx, o));
    mx = fmaxf(mx, bd);
    float p = expf(sc - mx), pb = expf(bd - mx);
    float ps = p;
    #pragma unroll
    for (int o = 16; o > 0; o >>= 1) ps += __shfl_xor_sync(0xffffffffu, ps, o);
    float inv = 1.0f / (ps + pb);
    p *= inv;

    float acc = (pb * inv) * blank_v[ch];
    #pragma unroll
    for (int m = 0; m < 32; m++) {
        float pm = __shfl_sync(0xffffffffu, p, m);
        acc += pm * g_v[(size_t)(rowbase + s_idx[m]) * C_ + ch];
    }

    __nv_bfloat16 hi = __float2bfloat16(acc);
    __nv_bfloat16 lo = __float2bfloat16(acc - __bfloat162float(hi));
    g_ao[(size_t)tok * 512 + ch] = hi;
    g_ao[(size_t)tok * 512 + 256 + ch] = lo;
}

// ---- launch ----
extern "C" void kernel_launch(void* const* d_in, const int* in_sizes, int n_in,
                              void* d_out, int out_size)
{
    const float* feat  = (const float*)d_in[0];
    const int*   midx  = (const int*)  d_in[1];
    const float* cmask = (const float*)d_in[2];
    const int*   peidx = (const int*)  d_in[3];
    const float* pre   = (const float*)d_in[5];
    const float* n1w   = (const float*)d_in[6];
    const float* n1b   = (const float*)d_in[7];
    const float* qw    = (const float*)d_in[8];
    const float* qb    = (const float*)d_in[9];
    const float* kvw   = (const float*)d_in[10];
    const float* kvb   = (const float*)d_in[11];
    const float* bk    = (const float*)d_in[12];
    const float* bv    = (const float*)d_in[13];
    const float* pew   = (const float*)d_in[14];
    const float* peb   = (const float*)d_in[15];
    const float* pjw   = (const float*)d_in[16];
    const float* pjb   = (const float*)d_in[17];
    const float* n2w   = (const float*)d_in[18];
    const float* n2b   = (const float*)d_in[19];
    const float* f1w   = (const float*)d_in[20];
    const float* f1b   = (const float*)d_in[21];
    const float* f2w   = (const float*)d_in[22];
    const float* f2b   = (const float*)d_in[23];
    float* out = (float*)d_out;

    cudaFuncSetAttribute(mm_kernel<0>, cudaFuncAttributeMaxDynamicSharedMemorySize, SMEM_BYTES);
    cudaFuncSetAttribute(mm_kernel<1>, cudaFuncAttributeMaxDynamicSharedMemorySize, SMEM_BYTES);
    cudaFuncSetAttribute(mm_kernel<2>, cudaFuncAttributeMaxDynamicSharedMemorySize, SMEM_BYTES);
    cudaFuncSetAttribute(mm_kernel<3>, cudaFuncAttributeMaxDynamicSharedMemorySize, SMEM_BYTES);

    // 0: fused prologue (LN1 + weight pack + bias/pe)
    prologue_kernel<<<PROLOGUE_GRID, 256>>>(feat, n1w, n1b, qw, kvw, pjw, f1w, f2w,
                                            qb, kvb, pre, pew, peb);
    // 1: QKV GEMM
    mm_kernel<0><<<dim3(6, 128), 256, SMEM_BYTES>>>(nullptr, nullptr, nullptr);
    // 2: attention
    attn_kernel<<<NTOK, 256>>>(midx, peidx, cmask, bk, bv);
    // 3: proj + residual
    mm_kernel<1><<<dim3(2, 128), 256, SMEM_BYTES>>>(pjb, feat, nullptr);
    // 4: LN2
    ln2_kernel<<<(NTOK * 32) / 256, 256>>>(n2w, n2b);
    // 5: fc1 + gelu
    mm_kernel<2><<<dim3(4, 128), 256, SMEM_BYTES>>>(f1b, nullptr, nullptr);
    // 6: fc2 + residual
    mm_kernel<3><<<dim3(2, 128), 256, SMEM_BYTES>>>(f2b, nullptr, out);
}